// round 3
// baseline (speedup 1.0000x reference)
#include <cuda_runtime.h>
#include <cstdint>

// ---------------------------------------------------------------------------
// Problem constants
//   x:       (32, 512, 56, 56) f32
//   bn_*:    (1024,) f32
//   conv_w:  (256, 1024) f32
//   out:     (32, 256, 28, 28) f32
//
// Rewrite:  pool(W . relu(bn(cat))) == W . pool(relu(bn(cat)))
//   hbar[c2][b][ij]  (K-major A^T, M = b*784+ij = 25088, K = 1024)
//   out[b][n][ij] = sum_k hbar[k][b*784+ij] * conv_w[n][k]
// ---------------------------------------------------------------------------

#define PO 784         // 28*28
#define M_TOT 25088    // 32*784
#define K_TOT 1024
#define N_TOT 256
#define TOT_H (1024 * 32 * 784)

__device__ float g_hbar[25690112];   // [1024][32][784]  = A^T [K][M]
__device__ float g_wt[262144];       // [1024][256]      = W^T [K][N]

// resample map: p//7*6 + min(p%7,5), then +4 for the crop offset
__device__ __forceinline__ int rmap(int p) {
    int q = p / 7;
    int r = p - q * 7;
    return q * 6 + (r < 5 ? r : 5) + 4;
}

// ---------------------------------------------------------------------------
// Pass 0: transpose conv_w [256][1024] -> g_wt [1024][256]
// ---------------------------------------------------------------------------
__global__ void transW_kernel(const float* __restrict__ w) {
    int e = blockIdx.x * 256 + threadIdx.x;
    if (e < 262144) {
        int n = e & 255;
        int k = e >> 8;
        g_wt[e] = w[n * 1024 + k];
    }
}

// ---------------------------------------------------------------------------
// Pass 1: fused gather + BN + ReLU + 2x2 avg pool -> g_hbar [c2][b][ij]
// ---------------------------------------------------------------------------
__global__ void pass1_kernel(const float* __restrict__ x,
                             const float* __restrict__ gamma,
                             const float* __restrict__ beta,
                             const float* __restrict__ mean,
                             const float* __restrict__ var) {
    int e = blockIdx.x * 256 + threadIdx.x;
    if (e >= TOT_H) return;
    int ij = e % PO;
    int t  = e / PO;
    int b  = t & 31;
    int c2 = t >> 5;
    int i = ij / 28;
    int j = ij - i * 28;

    float inv  = gamma[c2] * rsqrtf(var[c2] + 1e-5f);
    float bias = fmaf(-mean[c2], inv, beta[c2]);

    const float* xp = x + (size_t)(b * 512 + (c2 & 511)) * 3136;

    float v00, v01, v10, v11;
    if (c2 < 512) {
        // direct channel: rows 2i, 2i+1, cols 2j, 2j+1 -> two float2 loads
        float2 a0 = *(const float2*)(xp + (2 * i) * 56 + 2 * j);
        float2 a1 = *(const float2*)(xp + (2 * i + 1) * 56 + 2 * j);
        v00 = a0.x; v01 = a0.y; v10 = a1.x; v11 = a1.y;
    } else {
        // upsampled channel: gather through the resample map
        int r0 = rmap(2 * i), r1 = rmap(2 * i + 1);
        int q0 = rmap(2 * j), q1 = rmap(2 * j + 1);
        v00 = xp[r0 * 56 + q0]; v01 = xp[r0 * 56 + q1];
        v10 = xp[r1 * 56 + q0]; v11 = xp[r1 * 56 + q1];
    }
    float s = fmaxf(fmaf(v00, inv, bias), 0.0f)
            + fmaxf(fmaf(v01, inv, bias), 0.0f)
            + fmaxf(fmaf(v10, inv, bias), 0.0f)
            + fmaxf(fmaf(v11, inv, bias), 0.0f);
    g_hbar[e] = 0.25f * s;
}

// ---------------------------------------------------------------------------
// Pass 2: GEMM  out[m][n] = sum_k A^T[k][m] * W^T[k][n]
// fp32 via packed fma.rn.f32x2 (2x the 3-reg FFMA rate on sm_103a)
// BM=128, BN=64, BK=16, 256 threads, per-thread 8(m) x 4(n) as 4 m-pairs.
// ---------------------------------------------------------------------------
__device__ __forceinline__ unsigned long long dup2(float f) {
    unsigned u = __float_as_uint(f);
    unsigned long long r;
    asm("mov.b64 %0, {%1, %1};" : "=l"(r) : "r"(u));
    return r;
}
__device__ __forceinline__ void fma2(unsigned long long& d,
                                     unsigned long long a,
                                     unsigned long long b) {
    asm("fma.rn.f32x2 %0, %1, %2, %0;" : "+l"(d) : "l"(a), "l"(b));
}
__device__ __forceinline__ float lo32(unsigned long long v) {
    return __uint_as_float((unsigned)(v & 0xffffffffu));
}
__device__ __forceinline__ float hi32(unsigned long long v) {
    return __uint_as_float((unsigned)(v >> 32));
}

#define BM 128
#define BN 64
#define BK 16
#define NKT 64   // 1024 / 16

__global__ __launch_bounds__(256, 2) void gemm_kernel(float* __restrict__ out) {
    __shared__ float As[BK][BM];   // 8 KB
    __shared__ float Bs[BK][BN];   // 4 KB

    const int m0  = blockIdx.x * BM;
    const int n0  = blockIdx.y * BN;
    const int tid = threadIdx.x;
    const int tx  = tid & 15;   // m micro-index (16 threads cover 128 rows as 2 groups)
    const int ty  = tid >> 4;   // n micro-index (16 threads cover 64 cols)

    // global tile-load assignments (all fully coalesced, K-major sources)
    const int a_kr = tid >> 5;          // 0..7 (also +8)
    const int a_lc = (tid & 31) << 2;   // float4 column in [0,128)
    const int b_kr = tid >> 4;          // 0..15
    const int b_lc = (tid & 15) << 2;   // float4 column in [0,64)

    const float* Ag = g_hbar + (size_t)a_kr * M_TOT + m0 + a_lc;
    const float* Bg = g_wt   + (size_t)b_kr * N_TOT + n0 + b_lc;

    unsigned long long acc[4][4];
#pragma unroll
    for (int i = 0; i < 4; ++i)
#pragma unroll
        for (int j = 0; j < 4; ++j) acc[i][j] = 0ULL;

    // prefetch tile 0 into registers
    float4 pa0 = *(const float4*)(Ag);
    float4 pa1 = *(const float4*)(Ag + 8 * M_TOT);
    float4 pb  = *(const float4*)(Bg);

    for (int kt = 0; kt < NKT; ++kt) {
        // commit prefetched tile to smem
        *(float4*)&As[a_kr][a_lc]     = pa0;
        *(float4*)&As[a_kr + 8][a_lc] = pa1;
        *(float4*)&Bs[b_kr][b_lc]     = pb;
        __syncthreads();

        // issue next tile's global loads (overlap with compute below)
        if (kt + 1 < NKT) {
            const float* Ag2 = Ag + (size_t)(kt + 1) * BK * M_TOT;
            pa0 = *(const float4*)(Ag2);
            pa1 = *(const float4*)(Ag2 + 8 * M_TOT);
            pb  = *(const float4*)(Bg + (size_t)(kt + 1) * BK * N_TOT);
        }

#pragma unroll
        for (int kk = 0; kk < BK; ++kk) {
            // a: two conflict-free LDS.128, natural (m,m+1) pairs
            ulonglong2 a0 = *(const ulonglong2*)&As[kk][tx * 4];
            ulonglong2 a1 = *(const ulonglong2*)&As[kk][64 + tx * 4];
            // b: one broadcast LDS.128, duplicate into (b,b) on the ALU pipe
            float4 bf = *(const float4*)&Bs[kk][ty * 4];
            unsigned long long b0 = dup2(bf.x);
            unsigned long long b1 = dup2(bf.y);
            unsigned long long b2 = dup2(bf.z);
            unsigned long long b3 = dup2(bf.w);

            fma2(acc[0][0], a0.x, b0); fma2(acc[0][1], a0.x, b1);
            fma2(acc[0][2], a0.x, b2); fma2(acc[0][3], a0.x, b3);
            fma2(acc[1][0], a0.y, b0); fma2(acc[1][1], a0.y, b1);
            fma2(acc[1][2], a0.y, b2); fma2(acc[1][3], a0.y, b3);
            fma2(acc[2][0], a1.x, b0); fma2(acc[2][1], a1.x, b1);
            fma2(acc[2][2], a1.x, b2); fma2(acc[2][3], a1.x, b3);
            fma2(acc[3][0], a1.y, b0); fma2(acc[3][1], a1.y, b1);
            fma2(acc[3][2], a1.y, b2); fma2(acc[3][3], a1.y, b3);
        }
        __syncthreads();
    }

    // epilogue: out[b][n][ij], vectorized float4 along m (784 % 4 == 0 so a
    // 4-aligned m group never crosses a batch/ij row boundary)
    const int mA  = m0 + tx * 4;
    const int mB  = mA + 64;
    const int bA  = mA / 784, ijA = mA - bA * 784;
    const int bB  = mB / 784, ijB = mB - bB * 784;
#pragma unroll
    for (int j = 0; j < 4; ++j) {
        int n = n0 + ty * 4 + j;
        float4 r0 = make_float4(lo32(acc[0][j]), hi32(acc[0][j]),
                                lo32(acc[1][j]), hi32(acc[1][j]));
        float4 r1 = make_float4(lo32(acc[2][j]), hi32(acc[2][j]),
                                lo32(acc[3][j]), hi32(acc[3][j]));
        *(float4*)&out[((size_t)bA * 256 + n) * 784 + ijA] = r0;
        *(float4*)&out[((size_t)bB * 256 + n) * 784 + ijB] = r1;
    }
}

// ---------------------------------------------------------------------------
extern "C" void kernel_launch(void* const* d_in, const int* in_sizes, int n_in,
                              void* d_out, int out_size) {
    (void)in_sizes; (void)n_in; (void)out_size;
    const float* x     = (const float*)d_in[0];
    const float* gamma = (const float*)d_in[1];
    const float* beta  = (const float*)d_in[2];
    const float* mean  = (const float*)d_in[3];
    const float* var   = (const float*)d_in[4];
    const float* w     = (const float*)d_in[5];
    float* out = (float*)d_out;

    transW_kernel<<<1024, 256>>>(w);
    pass1_kernel<<<(TOT_H + 255) / 256, 256>>>(x, gamma, beta, mean, var);
    dim3 g(M_TOT / BM, N_TOT / BN);   // (196, 4)
    gemm_kernel<<<g, 256>>>(out);
}

// round 9
// speedup vs baseline: 1.4891x; 1.4891x over previous
#include <cuda_runtime.h>
#include <cuda_bf16.h>
#include <cstdint>

#define M_TOT 25088
#define ASTG 20480          // A bytes/stage (hi+lo), rows padded to 80B
#define BSTG 17408          // B bytes/stage (hi+lo), 16 kp-rows padded to 544B
#define STG  37888
#define DSMEM 75776

__device__ __align__(256) uint32_t g_Bh[12845056];        // hbar hi [512 kp][25088 m] k-pair packed
__device__ __align__(256) uint32_t g_Bl[12845056];        // hbar lo
__device__ __align__(256) unsigned short g_wh[262144];    // W hi [n][k]
__device__ __align__(256) unsigned short g_wl[262144];    // W lo [n][k]

__device__ __forceinline__ int rmap(int p) { int q = p / 7, r = p - q * 7; return q * 6 + (r < 5 ? r : 5) + 4; }
__device__ __forceinline__ uint32_t smem_u32(const void* p) {
    uint32_t a; asm("{ .reg .u64 t; cvta.to.shared.u64 t, %1; cvt.u32.u64 %0, t; }" : "=r"(a) : "l"(p)); return a;
}
__device__ __forceinline__ void hl_split(float v, unsigned short& h, unsigned short& l) {
    __nv_bfloat16 bh = __float2bfloat16(v);
    __nv_bfloat16 bl = __float2bfloat16(v - __bfloat162float(bh));
    h = *(unsigned short*)&bh; l = *(unsigned short*)&bl;
}
__device__ __forceinline__ uint32_t lds32(uint32_t a) {
    uint32_t v; asm volatile("ld.shared.u32 %0, [%1];" : "=r"(v) : "r"(a)); return v;
}

#define MMA(c, a, b0, b1) asm volatile( \
    "mma.sync.aligned.m16n8k16.row.col.f32.bf16.bf16.f32 {%0,%1,%2,%3}, {%4,%5,%6,%7}, {%8,%9}, {%0,%1,%2,%3};" \
    : "+f"((c)[0]), "+f"((c)[1]), "+f"((c)[2]), "+f"((c)[3]) \
    : "r"((a)[0]), "r"((a)[1]), "r"((a)[2]), "r"((a)[3]), "r"(b0), "r"(b1))
#define CPA(d, s) asm volatile("cp.async.cg.shared.global [%0], [%1], 16;" :: "r"(d), "l"(s))

// ---- pass0: split W into bf16 hi/lo, [n][k] row-major -----------------------
__global__ void wprep_kernel(const float* __restrict__ w) {
    int i = blockIdx.x * 256 + threadIdx.x;      // 0..131071, 2 elems each
    float2 v = *(const float2*)(w + (size_t)i * 2);
    unsigned short h0, l0, h1, l1;
    hl_split(v.x, h0, l0); hl_split(v.y, h1, l1);
    *(uint32_t*)(g_wh + (size_t)i * 2) = h0 | ((uint32_t)h1 << 16);
    *(uint32_t*)(g_wl + (size_t)i * 2) = l0 | ((uint32_t)l1 << 16);
}

// ---- pass1: channel-pair resident gather+BN+ReLU+pool -> packed u32 [kp][m] -
__global__ __launch_bounds__(256) void pass1_kernel(const float* __restrict__ x,
        const float* __restrict__ gamma, const float* __restrict__ beta,
        const float* __restrict__ mean, const float* __restrict__ var) {
    __shared__ float s[2][3136];
    int t = threadIdx.x, blk = blockIdx.x;
    int b = blk & 31, cp = blk >> 5;             // cp 0..255 -> channels 2cp, 2cp+1
#pragma unroll
    for (int pl = 0; pl < 2; ++pl) {
        const float4* xp4 = (const float4*)(x + ((size_t)(b * 512 + 2 * cp + pl)) * 3136);
        float4* s4 = (float4*)s[pl];
        // 784 float4 = 3*256 + 16  (FIX: previous rounds dropped the last 16)
        s4[t] = xp4[t];
        s4[t + 256] = xp4[t + 256];
        s4[t + 512] = xp4[t + 512];
        if (t < 16) s4[t + 768] = xp4[t + 768];
    }
    __syncthreads();
    if (t >= 196) return;
    int ij0 = 4 * t, i = ij0 / 28, j0 = ij0 - i * 28;
#pragma unroll
    for (int g = 0; g < 2; ++g) {                // g=0 direct, g=1 gathered (+512)
        unsigned short hh[2][4], ll[2][4];
#pragma unroll
        for (int pl = 0; pl < 2; ++pl) {
            int c2 = 2 * cp + pl + g * 512;
            float inv = gamma[c2] * rsqrtf(var[c2] + 1e-5f);
            float bias = fmaf(-mean[c2], inv, beta[c2]);
            const float* r0; const float* r1;
            if (!g) { r0 = s[pl] + (2 * i) * 56; r1 = r0 + 56; }
            else { r0 = s[pl] + rmap(2 * i) * 56; r1 = s[pl] + rmap(2 * i + 1) * 56; }
#pragma unroll
            for (int u = 0; u < 4; ++u) {
                int jj = j0 + u;
                int q0 = g ? rmap(2 * jj) : 2 * jj;
                int q1 = g ? rmap(2 * jj + 1) : 2 * jj + 1;
                float o = 0.25f * (fmaxf(fmaf(r0[q0], inv, bias), 0.0f) + fmaxf(fmaf(r0[q1], inv, bias), 0.0f)
                                 + fmaxf(fmaf(r1[q0], inv, bias), 0.0f) + fmaxf(fmaf(r1[q1], inv, bias), 0.0f));
                hl_split(o, hh[pl][u], ll[pl][u]);
            }
        }
        size_t base = (size_t)(g * 256 + cp) * M_TOT + b * 784 + ij0;
        uint4 vh, vl;
        vh.x = hh[0][0] | ((uint32_t)hh[1][0] << 16); vh.y = hh[0][1] | ((uint32_t)hh[1][1] << 16);
        vh.z = hh[0][2] | ((uint32_t)hh[1][2] << 16); vh.w = hh[0][3] | ((uint32_t)hh[1][3] << 16);
        vl.x = ll[0][0] | ((uint32_t)ll[1][0] << 16); vl.y = ll[0][1] | ((uint32_t)ll[1][1] << 16);
        vl.z = ll[0][2] | ((uint32_t)ll[1][2] << 16); vl.w = ll[0][3] | ((uint32_t)ll[1][3] << 16);
        *(uint4*)(g_Bh + base) = vh;
        *(uint4*)(g_Bl + base) = vl;
    }
}

// ---- pass2: HMMA GEMM, manual fragments. D[n][m] = sum_k W[n][k]*hbar[k][m] -
__global__ __launch_bounds__(256, 2) void gemm_kernel(float* __restrict__ out) {
    extern __shared__ char dsm[];
    const uint32_t sb = smem_u32(dsm);
    const int tid = threadIdx.x;
    const int lane = tid & 31, wid = tid >> 5;
    const int wn = wid >> 2, wm = wid & 3;          // warp tile: 64n x 32m
    const int n0 = (blockIdx.x & 1) * 128;
    const int m0 = (blockIdx.x >> 1) * 128;
    const int tg = lane & 3, gp = lane >> 2;        // threadID_in_group, groupID

    float c[4][4][4];
#pragma unroll
    for (int a = 0; a < 4; ++a)
#pragma unroll
        for (int b = 0; b < 4; ++b)
#pragma unroll
            for (int d = 0; d < 4; ++d) c[a][b][d] = 0.0f;

    auto load_stage = [&](int st, int kt) {
        uint32_t ab = sb + st * STG, bb = ab + ASTG;
#pragma unroll
        for (int it = 0; it < 4; ++it) {
            int e = tid + it * 256;                       // 0..1023
            {   // A: 2(hilo) x 128 n-rows x 4 chunks of 16B (k 0..31)
                int hl = e >> 9, r = (e >> 2) & 127, q = e & 3;
                uint32_t d = ab + hl * 10240 + r * 80 + q * 16;
                const unsigned short* sp = (hl ? g_wl : g_wh) + (size_t)(n0 + r) * 1024 + kt * 32 + q * 8;
                CPA(d, sp);
            }
            {   // B: 2(hilo) x 16 kp-rows x 32 chunks of 16B (m 0..127 as u32)
                int hl = e >> 9, r = (e >> 5) & 15, q = e & 31;
                uint32_t d = bb + hl * 8704 + r * 544 + q * 16;
                const uint32_t* sp = (hl ? g_Bl : g_Bh) + (size_t)(kt * 16 + r) * M_TOT + m0 + q * 4;
                CPA(d, sp);
            }
        }
        asm volatile("cp.async.commit_group;");
    };

    auto compute = [&](int st) {
        uint32_t ab = sb + st * STG, bb = ab + ASTG;
#pragma unroll
        for (int ks = 0; ks < 2; ++ks) {
            // B fragments: b0 at kp = ks*8+tg, b1 at kp+4; col = wm*32 + nj*8 + gp
            uint32_t bh0[4], bh1[4], bl0[4], bl1[4];
#pragma unroll
            for (int nj = 0; nj < 4; ++nj) {
                uint32_t off = bb + (ks * 8 + tg) * 544 + (wm * 32 + nj * 8 + gp) * 4;
                bh0[nj] = lds32(off);          bh1[nj] = lds32(off + 4 * 544);
                bl0[nj] = lds32(off + 8704);   bl1[nj] = lds32(off + 8704 + 4 * 544);
            }
#pragma unroll
            for (int mi = 0; mi < 4; ++mi) {
                // A fragments: row = wn*64+mi*16+gp(+8), k = ks*16 + 2*tg (+8)
                uint32_t ah[4], al[4];
                uint32_t aa = ab + (wn * 64 + mi * 16 + gp) * 80 + ks * 32 + tg * 4;
                ah[0] = lds32(aa);        ah[1] = lds32(aa + 640);
                ah[2] = lds32(aa + 16);   ah[3] = lds32(aa + 656);
                al[0] = lds32(aa + 10240);        al[1] = lds32(aa + 10240 + 640);
                al[2] = lds32(aa + 10240 + 16);   al[3] = lds32(aa + 10240 + 656);
#pragma unroll
                for (int nj = 0; nj < 4; ++nj) {
                    MMA(c[mi][nj], ah, bh0[nj], bh1[nj]);
                    MMA(c[mi][nj], ah, bl0[nj], bl1[nj]);
                    MMA(c[mi][nj], al, bh0[nj], bh1[nj]);
                }
            }
        }
    };

    load_stage(0, 0);
    for (int t = 0; t < 32; ++t) {
        if (t + 1 < 32) {
            load_stage((t + 1) & 1, t + 1);
            asm volatile("cp.async.wait_group 1;");
        } else {
            asm volatile("cp.async.wait_group 0;");
        }
        __syncthreads();
        compute(t & 1);
        __syncthreads();
    }

    // epilogue: c fragment (row=gp, col=2*tg) -> smem transpose -> coalesced stores
    float* ep = (float*)dsm;                    // [128 n][132 m] f32
#pragma unroll
    for (int mi = 0; mi < 4; ++mi)
#pragma unroll
        for (int nj = 0; nj < 4; ++nj) {
            int n1 = wn * 64 + mi * 16 + gp;
            int m1 = wm * 32 + nj * 8 + tg * 2;
            *(float2*)&ep[n1 * 132 + m1] = make_float2(c[mi][nj][0], c[mi][nj][1]);
            *(float2*)&ep[(n1 + 8) * 132 + m1] = make_float2(c[mi][nj][2], c[mi][nj][3]);
        }
    __syncthreads();
#pragma unroll
    for (int it = 0; it < 16; ++it) {
        int e = tid + it * 256;                 // 0..4095
        int row = e >> 5, q = e & 31;
        int mg = m0 + q * 4;
        int bb2 = mg / 784, ij = mg - bb2 * 784;
        float4 v = *(float4*)&ep[row * 132 + q * 4];
        *(float4*)&out[((size_t)bb2 * 256 + n0 + row) * 784 + ij] = v;
    }
}

extern "C" void kernel_launch(void* const* d_in, const int* in_sizes, int n_in,
                              void* d_out, int out_size) {
    (void)in_sizes; (void)n_in; (void)out_size;
    const float* x     = (const float*)d_in[0];
    const float* gamma = (const float*)d_in[1];
    const float* beta  = (const float*)d_in[2];
    const float* mean  = (const float*)d_in[3];
    const float* var   = (const float*)d_in[4];
    const float* w     = (const float*)d_in[5];
    float* out = (float*)d_out;

    cudaFuncSetAttribute(gemm_kernel, cudaFuncAttributeMaxDynamicSharedMemorySize, DSMEM);
    wprep_kernel<<<512, 256>>>(w);
    pass1_kernel<<<8192, 256>>>(x, gamma, beta, mean, var);
    gemm_kernel<<<392, 256, DSMEM>>>(out);
}

// round 10
// speedup vs baseline: 3.5640x; 2.3935x over previous
#include <cuda_runtime.h>
#include <cuda_fp16.h>
#include <cstdint>

#define M_TOT 25088
#define ASTG 10240          // A bytes/stage, 128 rows padded to 80B
#define BSTG 8704           // B bytes/stage, 16 kp-rows padded to 544B
#define STG  18944
#define DSMEM 37888

__device__ __align__(256) uint32_t g_Bh[12845056];        // hbar fp16 [512 kp][25088 m], k-pair packed
__device__ __align__(256) unsigned short g_wh[262144];    // W fp16 [n][k]

__device__ __forceinline__ int rmap(int p) { int q = p / 7, r = p - q * 7; return q * 6 + (r < 5 ? r : 5) + 4; }
__device__ __forceinline__ uint32_t smem_u32(const void* p) {
    uint32_t a; asm("{ .reg .u64 t; cvta.to.shared.u64 t, %1; cvt.u32.u64 %0, t; }" : "=r"(a) : "l"(p)); return a;
}
__device__ __forceinline__ uint32_t lds32(uint32_t a) {
    uint32_t v; asm volatile("ld.shared.u32 %0, [%1];" : "=r"(v) : "r"(a)); return v;
}

#define MMA(c, a, b0, b1) asm volatile( \
    "mma.sync.aligned.m16n8k16.row.col.f32.f16.f16.f32 {%0,%1,%2,%3}, {%4,%5,%6,%7}, {%8,%9}, {%0,%1,%2,%3};" \
    : "+f"((c)[0]), "+f"((c)[1]), "+f"((c)[2]), "+f"((c)[3]) \
    : "r"((a)[0]), "r"((a)[1]), "r"((a)[2]), "r"((a)[3]), "r"(b0), "r"(b1))
#define CPA(d, s) asm volatile("cp.async.cg.shared.global [%0], [%1], 16;" :: "r"(d), "l"(s))

// ---- pass0: W f32 -> fp16 [n][k] --------------------------------------------
__global__ void wprep_kernel(const float* __restrict__ w) {
    int i = blockIdx.x * 256 + threadIdx.x;      // 0..65535, 4 elems each
    float4 v = *(const float4*)(w + (size_t)i * 4);
    __half2 p0 = __floats2half2_rn(v.x, v.y);
    __half2 p1 = __floats2half2_rn(v.z, v.w);
    *(uint2*)(g_wh + (size_t)i * 4) = make_uint2(*(uint32_t*)&p0, *(uint32_t*)&p1);
}

// ---- pass1: channel-pair resident gather+BN+ReLU+pool -> packed fp16 [kp][m] -
__global__ __launch_bounds__(256) void pass1_kernel(const float* __restrict__ x,
        const float* __restrict__ gamma, const float* __restrict__ beta,
        const float* __restrict__ mean, const float* __restrict__ var) {
    __shared__ float s[2][3136];
    int t = threadIdx.x, blk = blockIdx.x;
    int b = blk & 31, cp = blk >> 5;             // cp 0..255 -> channels 2cp, 2cp+1
#pragma unroll
    for (int pl = 0; pl < 2; ++pl) {
        const float4* xp4 = (const float4*)(x + ((size_t)(b * 512 + 2 * cp + pl)) * 3136);
        float4* s4 = (float4*)s[pl];
        // 784 float4 = 3*256 + 16
        s4[t] = xp4[t];
        s4[t + 256] = xp4[t + 256];
        s4[t + 512] = xp4[t + 512];
        if (t < 16) s4[t + 768] = xp4[t + 768];
    }
    __syncthreads();
    if (t >= 196) return;
    int ij0 = 4 * t, i = ij0 / 28, j0 = ij0 - i * 28;
#pragma unroll
    for (int g = 0; g < 2; ++g) {                // g=0 direct, g=1 gathered (+512)
        unsigned short hh[2][4];
#pragma unroll
        for (int pl = 0; pl < 2; ++pl) {
            int c2 = 2 * cp + pl + g * 512;
            float inv = gamma[c2] * rsqrtf(var[c2] + 1e-5f);
            float bias = fmaf(-mean[c2], inv, beta[c2]);
            const float* r0; const float* r1;
            if (!g) { r0 = s[pl] + (2 * i) * 56; r1 = r0 + 56; }
            else { r0 = s[pl] + rmap(2 * i) * 56; r1 = s[pl] + rmap(2 * i + 1) * 56; }
#pragma unroll
            for (int u = 0; u < 4; ++u) {
                int jj = j0 + u;
                int q0 = g ? rmap(2 * jj) : 2 * jj;
                int q1 = g ? rmap(2 * jj + 1) : 2 * jj + 1;
                float o = 0.25f * (fmaxf(fmaf(r0[q0], inv, bias), 0.0f) + fmaxf(fmaf(r0[q1], inv, bias), 0.0f)
                                 + fmaxf(fmaf(r1[q0], inv, bias), 0.0f) + fmaxf(fmaf(r1[q1], inv, bias), 0.0f));
                __half hv = __float2half_rn(o);
                hh[pl][u] = *(unsigned short*)&hv;
            }
        }
        size_t base = (size_t)(g * 256 + cp) * M_TOT + b * 784 + ij0;
        uint4 vh;
        vh.x = hh[0][0] | ((uint32_t)hh[1][0] << 16); vh.y = hh[0][1] | ((uint32_t)hh[1][1] << 16);
        vh.z = hh[0][2] | ((uint32_t)hh[1][2] << 16); vh.w = hh[0][3] | ((uint32_t)hh[1][3] << 16);
        *(uint4*)(g_Bh + base) = vh;
    }
}

// ---- pass2: fp16 HMMA GEMM, manual fragments. D[n][m] = sum_k W[n][k]*hbar[k][m]
__global__ __launch_bounds__(256, 2) void gemm_kernel(float* __restrict__ out) {
    extern __shared__ char dsm[];
    const uint32_t sb = smem_u32(dsm);
    const int tid = threadIdx.x;
    const int lane = tid & 31, wid = tid >> 5;
    const int wn = wid >> 2, wm = wid & 3;          // warp tile: 64n x 32m
    const int n0 = (blockIdx.x & 1) * 128;
    const int m0 = (blockIdx.x >> 1) * 128;
    const int tg = lane & 3, gp = lane >> 2;        // threadID_in_group, groupID

    float c[4][4][4];
#pragma unroll
    for (int a = 0; a < 4; ++a)
#pragma unroll
        for (int b = 0; b < 4; ++b)
#pragma unroll
            for (int d = 0; d < 4; ++d) c[a][b][d] = 0.0f;

    auto load_stage = [&](int st, int kt) {
        uint32_t ab = sb + st * STG, bb = ab + ASTG;
#pragma unroll
        for (int it = 0; it < 2; ++it) {
            int e = tid + it * 256;                       // 0..511
            {   // A: 128 n-rows x 4 chunks of 16B (k 0..31)
                int r = e >> 2, q = e & 3;
                CPA(ab + r * 80 + q * 16, g_wh + (size_t)(n0 + r) * 1024 + kt * 32 + q * 8);
            }
            {   // B: 16 kp-rows x 32 chunks of 16B (m 0..127 as u32)
                int r = e >> 5, q = e & 31;
                CPA(bb + r * 544 + q * 16, g_Bh + (size_t)(kt * 16 + r) * M_TOT + m0 + q * 4);
            }
        }
        asm volatile("cp.async.commit_group;");
    };

    auto compute = [&](int st) {
        uint32_t ab = sb + st * STG, bb = ab + ASTG;
#pragma unroll
        for (int ks = 0; ks < 2; ++ks) {
            // B fragments: b0 at kp = ks*8+tg, b1 at kp+4; col = wm*32 + nj*8 + gp
            uint32_t bh0[4], bh1[4];
#pragma unroll
            for (int nj = 0; nj < 4; ++nj) {
                uint32_t off = bb + (ks * 8 + tg) * 544 + (wm * 32 + nj * 8 + gp) * 4;
                bh0[nj] = lds32(off);
                bh1[nj] = lds32(off + 4 * 544);
            }
#pragma unroll
            for (int mi = 0; mi < 4; ++mi) {
                // A fragments: row = wn*64+mi*16+gp(+8), k = ks*16 + 2*tg (+8)
                uint32_t ah[4];
                uint32_t aa = ab + (wn * 64 + mi * 16 + gp) * 80 + ks * 32 + tg * 4;
                ah[0] = lds32(aa);        ah[1] = lds32(aa + 640);
                ah[2] = lds32(aa + 16);   ah[3] = lds32(aa + 656);
#pragma unroll
                for (int nj = 0; nj < 4; ++nj)
                    MMA(c[mi][nj], ah, bh0[nj], bh1[nj]);
            }
        }
    };

    load_stage(0, 0);
    for (int t = 0; t < 32; ++t) {
        if (t + 1 < 32) {
            load_stage((t + 1) & 1, t + 1);
            asm volatile("cp.async.wait_group 1;");
        } else {
            asm volatile("cp.async.wait_group 0;");
        }
        __syncthreads();
        compute(t & 1);
        __syncthreads();
    }

    // epilogue in two 64-row halves (fits 37888B smem): c frag -> smem -> coalesced
    float* ep = (float*)dsm;                    // [64 n][132 m] f32
#pragma unroll
    for (int h = 0; h < 2; ++h) {
        __syncthreads();
        if (wn == h) {
#pragma unroll
            for (int mi = 0; mi < 4; ++mi)
#pragma unroll
                for (int nj = 0; nj < 4; ++nj) {
                    int n1 = mi * 16 + gp;
                    int m1 = wm * 32 + nj * 8 + tg * 2;
                    *(float2*)&ep[n1 * 132 + m1] = make_float2(c[mi][nj][0], c[mi][nj][1]);
                    *(float2*)&ep[(n1 + 8) * 132 + m1] = make_float2(c[mi][nj][2], c[mi][nj][3]);
                }
        }
        __syncthreads();
#pragma unroll
        for (int it = 0; it < 8; ++it) {
            int e = tid + it * 256;             // 0..2047
            int row = e >> 5, q = e & 31;
            int mg = m0 + q * 4;
            int bb2 = mg / 784, ij = mg - bb2 * 784;
            float4 v = *(float4*)&ep[row * 132 + q * 4];
            *(float4*)&out[((size_t)bb2 * 256 + n0 + h * 64 + row) * 784 + ij] = v;
        }
    }
}

extern "C" void kernel_launch(void* const* d_in, const int* in_sizes, int n_in,
                              void* d_out, int out_size) {
    (void)in_sizes; (void)n_in; (void)out_size;
    const float* x     = (const float*)d_in[0];
    const float* gamma = (const float*)d_in[1];
    const float* beta  = (const float*)d_in[2];
    const float* mean  = (const float*)d_in[3];
    const float* var   = (const float*)d_in[4];
    const float* w     = (const float*)d_in[5];
    float* out = (float*)d_out;

    cudaFuncSetAttribute(gemm_kernel, cudaFuncAttributeMaxDynamicSharedMemorySize, DSMEM);
    wprep_kernel<<<256, 256>>>(w);
    pass1_kernel<<<8192, 256>>>(x, gamma, beta, mean, var);
    gemm_kernel<<<392, 256, DSMEM>>>(out);
}